// round 1
// baseline (speedup 1.0000x reference)
#include <cuda_runtime.h>

#define DIM 128
#define NMAX 100000
#define EMAX 600000

// ---------------- static device scratch (no allocations allowed) -------------
__device__ float g_agg[(size_t)NMAX * DIM];   // neighbor sum (reused both layers)
__device__ float g_cnt[NMAX];                 // in-degree (computed once, reused)
__device__ float g_h[(size_t)NMAX * DIM];     // relu(L2norm(conv1)) (pre-BN)
__device__ float g_bnsum[DIM];
__device__ float g_bnsq[DIM];
__device__ float g_scale[DIM];                // BN folded scale
__device__ float g_shift[DIM];                // BN folded shift
__device__ float g_preds_fb[NMAX];            // fallback sink if out layout differs

// ---------------- zero kernels ----------------------------------------------
__global__ void k_zero_all(int N) {
    const int stride = gridDim.x * blockDim.x;
    const int t = blockIdx.x * blockDim.x + threadIdx.x;
    const float4 z = make_float4(0.f, 0.f, 0.f, 0.f);
    const size_t tot4 = (size_t)N * (DIM / 4);
    for (size_t i = t; i < tot4; i += stride) ((float4*)g_agg)[i] = z;
    for (int i = t; i < N; i += stride) g_cnt[i] = 0.f;
    if (t < DIM) { g_bnsum[t] = 0.f; g_bnsq[t] = 0.f; }
}

__global__ void k_zero_agg(int N) {
    const int stride = gridDim.x * blockDim.x;
    const int t = blockIdx.x * blockDim.x + threadIdx.x;
    const float4 z = make_float4(0.f, 0.f, 0.f, 0.f);
    const size_t tot4 = (size_t)N * (DIM / 4);
    for (size_t i = t; i < tot4; i += stride) ((float4*)g_agg)[i] = z;
}

// ---------------- edge scatter (layer 1): agg += x[src], cnt += 1 ------------
__global__ void k_scatter1(const float* __restrict__ x,
                           const int* __restrict__ ei, int E) {
    const int warp = (blockIdx.x * blockDim.x + threadIdx.x) >> 5;
    const int lane = threadIdx.x & 31;
    const int nw = (gridDim.x * blockDim.x) >> 5;
    const int c = lane * 4;
    for (int e = warp; e < E; e += nw) {
        const int s = ei[e];
        const int d = ei[E + e];
        float4 v = *(const float4*)(x + (size_t)s * DIM + c);
        float* a = g_agg + (size_t)d * DIM + c;
        atomicAdd(a + 0, v.x);
        atomicAdd(a + 1, v.y);
        atomicAdd(a + 2, v.z);
        atomicAdd(a + 3, v.w);
        if (lane == 0) atomicAdd(&g_cnt[d], 1.0f);
    }
}

// ---------------- edge scatter (layer 2): agg += bn(h[src]) ------------------
__global__ void k_scatter2(const int* __restrict__ ei, int E) {
    const int warp = (blockIdx.x * blockDim.x + threadIdx.x) >> 5;
    const int lane = threadIdx.x & 31;
    const int nw = (gridDim.x * blockDim.x) >> 5;
    const int c = lane * 4;
    const float s0 = g_scale[c + 0], s1 = g_scale[c + 1],
                s2 = g_scale[c + 2], s3 = g_scale[c + 3];
    const float t0 = g_shift[c + 0], t1 = g_shift[c + 1],
                t2 = g_shift[c + 2], t3 = g_shift[c + 3];
    for (int e = warp; e < E; e += nw) {
        const int s = ei[e];
        const int d = ei[E + e];
        float4 v = *(const float4*)(g_h + (size_t)s * DIM + c);
        float* a = g_agg + (size_t)d * DIM + c;
        atomicAdd(a + 0, v.x * s0 + t0);
        atomicAdd(a + 1, v.y * s1 + t1);
        atomicAdd(a + 2, v.z * s2 + t2);
        atomicAdd(a + 3, v.w * s3 + t3);
    }
}

// ---------------- BN finalize: fold (gamma, beta, mu, var) into scale/shift --
__global__ void k_bnfin(const float* __restrict__ gamma,
                        const float* __restrict__ beta, int N) {
    const int f = threadIdx.x;
    const float invN = 1.0f / (float)N;
    const float mu = g_bnsum[f] * invN;
    const float var = g_bnsq[f] * invN - mu * mu;
    const float sc = gamma[f] / sqrtf(var + 1e-5f);
    g_scale[f] = sc;
    g_shift[f] = beta[f] - mu * sc;
}

// ---------------- fused SAGE linear + epilogue -------------------------------
// C[64 x 128] per block:  C = [mean | feat] @ [Wl ; Wr] + bias, then per-row
// L2-normalize.  L==1: relu, store to g_h, accumulate BN stats.
// L==2: feat = bn(g_h); store embed; preds = embed[:, :64] @ fcW + fcb.
template <int L>
__global__ void __launch_bounds__(256)
k_gemm(const float* __restrict__ xin,
       const float* __restrict__ Wl, const float* __restrict__ Wr,
       const float* __restrict__ bias,
       const float* __restrict__ fcW, const float* __restrict__ fcb,
       float* __restrict__ outp, float* __restrict__ preds, int N) {
    __shared__ float As[16][72];     // [k][row], stride 72 keeps 16B alignment
    __shared__ float Ws[16][128];    // [k][col]
    __shared__ float s_invc[64];
    __shared__ float s_sc[DIM];
    __shared__ float s_sh[DIM];
    __shared__ float s_sum[DIM];
    __shared__ float s_sq[DIM];

    const int tid = threadIdx.x;
    const int r0 = blockIdx.x * 64;
    const int w = tid >> 5;
    const int lane = tid & 31;

    if (tid < 64) {
        const int n = min(r0 + tid, N - 1);
        s_invc[tid] = 1.0f / fmaxf(g_cnt[n], 1.0f);
    }
    if (L == 2) {
        if (tid < DIM) { s_sc[tid] = g_scale[tid]; s_sh[tid] = g_shift[tid]; }
    } else {
        if (tid < DIM) { s_sum[tid] = 0.f; s_sq[tid] = 0.f; }
    }
    __syncthreads();

    float acc[8][4];
#pragma unroll
    for (int i = 0; i < 8; i++) {
        acc[i][0] = 0.f; acc[i][1] = 0.f; acc[i][2] = 0.f; acc[i][3] = 0.f;
    }

    const int lrow = tid >> 2;            // 0..63
    const int kq = (tid & 3) * 4;         // 0,4,8,12
    const int nrow = min(r0 + lrow, N - 1);
    const float* __restrict__ aggrow = g_agg + (size_t)nrow * DIM;
    const float* __restrict__ xrow =
        (L == 1 ? xin : (const float*)g_h) + (size_t)nrow * DIM;
    const float invc = s_invc[lrow];

    const int wc = lane * 4;              // 0..124
    const int w8 = w * 8;

    for (int kc = 0; kc < 2 * DIM; kc += 16) {
        // --- A tile: virtual A = [mean | feat] ---
        {
            const int k = kc + kq;
            float4 v;
            if (k < DIM) {
                v = *(const float4*)(aggrow + k);
                v.x *= invc; v.y *= invc; v.z *= invc; v.w *= invc;
            } else {
                const int k2 = k - DIM;
                v = *(const float4*)(xrow + k2);
                if (L == 2) {
                    v.x = v.x * s_sc[k2 + 0] + s_sh[k2 + 0];
                    v.y = v.y * s_sc[k2 + 1] + s_sh[k2 + 1];
                    v.z = v.z * s_sc[k2 + 2] + s_sh[k2 + 2];
                    v.w = v.w * s_sc[k2 + 3] + s_sh[k2 + 3];
                }
            }
            As[kq + 0][lrow] = v.x;
            As[kq + 1][lrow] = v.y;
            As[kq + 2][lrow] = v.z;
            As[kq + 3][lrow] = v.w;
        }
        // --- W tile: stacked [Wl ; Wr] ---
#pragma unroll
        for (int h2 = 0; h2 < 2; h2++) {
            const int kk = w + h2 * 8;
            const int k = kc + kk;
            const float* Wp = (k < DIM) ? (Wl + (size_t)k * DIM + wc)
                                        : (Wr + (size_t)(k - DIM) * DIM + wc);
            *(float4*)&Ws[kk][wc] = *(const float4*)Wp;
        }
        __syncthreads();
#pragma unroll
        for (int kk = 0; kk < 16; kk++) {
            const float4 a0 = *(const float4*)&As[kk][w8];
            const float4 a1 = *(const float4*)&As[kk][w8 + 4];
            const float4 b4 = *(const float4*)&Ws[kk][wc];
            const float a[8] = {a0.x, a0.y, a0.z, a0.w, a1.x, a1.y, a1.z, a1.w};
#pragma unroll
            for (int i = 0; i < 8; i++) {
                acc[i][0] += a[i] * b4.x;
                acc[i][1] += a[i] * b4.y;
                acc[i][2] += a[i] * b4.z;
                acc[i][3] += a[i] * b4.w;
            }
        }
        __syncthreads();
    }

    // ---------------- epilogue ----------------
    const float4 bb = *(const float4*)(bias + wc);
    float fw0 = 0.f, fw1 = 0.f, fw2 = 0.f, fw3 = 0.f;
    if (L == 2) {
        if (wc + 0 < 64) fw0 = fcW[wc + 0];
        if (wc + 1 < 64) fw1 = fcW[wc + 1];
        if (wc + 2 < 64) fw2 = fcW[wc + 2];
        if (wc + 3 < 64) fw3 = fcW[wc + 3];
    }
    float* __restrict__ op =
        (L == 1) ? (float*)g_h : (outp ? outp : (float*)g_h);
    float* __restrict__ pp = preds ? preds : (float*)g_preds_fb;

    float ps[4] = {0.f, 0.f, 0.f, 0.f}, qs[4] = {0.f, 0.f, 0.f, 0.f};
#pragma unroll
    for (int i = 0; i < 8; i++) {
        const int r = r0 + w8 + i;
        float v0 = acc[i][0] + bb.x;
        float v1 = acc[i][1] + bb.y;
        float v2 = acc[i][2] + bb.z;
        float v3 = acc[i][3] + bb.w;
        float ss = v0 * v0 + v1 * v1 + v2 * v2 + v3 * v3;
#pragma unroll
        for (int o = 16; o > 0; o >>= 1) ss += __shfl_xor_sync(0xffffffffu, ss, o);
        const float inv = 1.0f / fmaxf(sqrtf(ss), 1e-12f);
        v0 *= inv; v1 *= inv; v2 *= inv; v3 *= inv;
        if (L == 1) {
            v0 = fmaxf(v0, 0.f); v1 = fmaxf(v1, 0.f);
            v2 = fmaxf(v2, 0.f); v3 = fmaxf(v3, 0.f);
            if (r < N) {  // uniform across warp
                *(float4*)(op + (size_t)r * DIM + wc) = make_float4(v0, v1, v2, v3);
                ps[0] += v0; ps[1] += v1; ps[2] += v2; ps[3] += v3;
                qs[0] += v0 * v0; qs[1] += v1 * v1;
                qs[2] += v2 * v2; qs[3] += v3 * v3;
            }
        } else {
            if (r < N) {  // uniform across warp
                *(float4*)(op + (size_t)r * DIM + wc) = make_float4(v0, v1, v2, v3);
                float pd = v0 * fw0 + v1 * fw1 + v2 * fw2 + v3 * fw3;
#pragma unroll
                for (int o = 16; o > 0; o >>= 1)
                    pd += __shfl_xor_sync(0xffffffffu, pd, o);
                if (lane == 0) pp[r] = pd + fcb[0];
            }
        }
    }
    if (L == 1) {
        atomicAdd(&s_sum[wc + 0], ps[0]); atomicAdd(&s_sum[wc + 1], ps[1]);
        atomicAdd(&s_sum[wc + 2], ps[2]); atomicAdd(&s_sum[wc + 3], ps[3]);
        atomicAdd(&s_sq[wc + 0], qs[0]);  atomicAdd(&s_sq[wc + 1], qs[1]);
        atomicAdd(&s_sq[wc + 2], qs[2]);  atomicAdd(&s_sq[wc + 3], qs[3]);
        __syncthreads();
        if (tid < DIM) {
            atomicAdd(&g_bnsum[tid], s_sum[tid]);
            atomicAdd(&g_bnsq[tid], s_sq[tid]);
        }
    }
}

// ---------------- launch ------------------------------------------------------
extern "C" void kernel_launch(void* const* d_in, const int* in_sizes, int n_in,
                              void* d_out, int out_size) {
    const float* x     = (const float*)d_in[0];
    const int*   ei    = (const int*)d_in[1];
    const float* W1l   = (const float*)d_in[2];
    const float* b1l   = (const float*)d_in[3];
    const float* W1r   = (const float*)d_in[4];
    const float* gamma = (const float*)d_in[5];
    const float* beta  = (const float*)d_in[6];
    const float* W2l   = (const float*)d_in[7];
    const float* b2l   = (const float*)d_in[8];
    const float* W2r   = (const float*)d_in[9];
    const float* fcW   = (const float*)d_in[10];
    const float* fcb   = (const float*)d_in[11];

    const int N = in_sizes[0] / DIM;
    const int E = in_sizes[1] / 2;

    // Output packing: tuple (preds[N], embed[N,128]) flattened in return order.
    float* predsP = nullptr;
    float* embedP = nullptr;
    const long long need = (long long)N * DIM + N;
    if ((long long)out_size >= need) {
        predsP = (float*)d_out;
        embedP = (float*)d_out + N;
    } else if ((long long)out_size >= (long long)N * DIM) {
        embedP = (float*)d_out;           // embed-only layout
    } else {
        predsP = (float*)d_out;           // preds-only layout
    }

    const int gz = 2048;
    const int gsc = 4096;
    const int gg = (N + 63) / 64;

    k_zero_all<<<gz, 256>>>(N);
    k_scatter1<<<gsc, 256>>>(x, ei, E);
    k_gemm<1><<<gg, 256>>>(x, W1l, W1r, b1l, nullptr, nullptr, nullptr, nullptr, N);
    k_bnfin<<<1, 128>>>(gamma, beta, N);
    k_zero_agg<<<gz, 256>>>(N);
    k_scatter2<<<gsc, 256>>>(ei, E);
    k_gemm<2><<<gg, 256>>>(nullptr, W2l, W2r, b2l, fcW, fcb, embedP, predsP, N);
}

// round 3
// speedup vs baseline: 1.5127x; 1.5127x over previous
#include <cuda_runtime.h>

#define DIM 128
#define NMAX 100000
#define EMAX 600000
#define NBMAX 128   // max scan blocks: ceil(100000/1024)=98

// ---------------- static device scratch --------------------------------------
__device__ float g_agg[(size_t)NMAX * DIM];
__device__ float g_cnt[NMAX];
__device__ float g_h[(size_t)NMAX * DIM];
__device__ float g_bnsum[DIM];
__device__ float g_bnsq[DIM];
__device__ float g_scale[DIM];
__device__ float g_shift[DIM];
__device__ float g_preds_fb[NMAX];
__device__ int   g_deg[NMAX];
__device__ int   g_rowptr[NMAX + 1];
__device__ int   g_fill[NMAX];
__device__ int   g_col[EMAX];
__device__ int   g_part[NBMAX];

// ---------------- CSR build ---------------------------------------------------
__global__ void k_init(int N) {
    const int t = blockIdx.x * blockDim.x + threadIdx.x;
    const int stride = gridDim.x * blockDim.x;
    for (int i = t; i < N; i += stride) g_deg[i] = 0;
    if (t < DIM) { g_bnsum[t] = 0.f; g_bnsq[t] = 0.f; }
}

__global__ void k_count(const int* __restrict__ ei, int E) {
    const int t = blockIdx.x * blockDim.x + threadIdx.x;
    const int stride = gridDim.x * blockDim.x;
    for (int e = t; e < E; e += stride) atomicAdd(&g_deg[ei[E + e]], 1);
}

// per-block partial sums over 1024-element chunks of g_deg
__global__ void k_scan_part(int N) {
    const int b = blockIdx.x, t = threadIdx.x;
    const int base = b * 1024 + t * 4;
    int s = 0;
#pragma unroll
    for (int i = 0; i < 4; i++) {
        const int idx = base + i;
        if (idx < N) s += g_deg[idx];
    }
#pragma unroll
    for (int o = 16; o > 0; o >>= 1) s += __shfl_xor_sync(0xffffffffu, s, o);
    __shared__ int ws[8];
    if ((t & 31) == 0) ws[t >> 5] = s;
    __syncthreads();
    if (t == 0) {
        int a = 0;
        for (int i = 0; i < 8; i++) a += ws[i];
        g_part[b] = a;
    }
}

// exclusive scan of block partials (single block)
__global__ void k_scan_top(int nb) {
    const int t = threadIdx.x;           // 128 threads
    const int lane = t & 31, w = t >> 5;
    int orig = (t < nb) ? g_part[t] : 0;
    int v = orig;
#pragma unroll
    for (int o = 1; o < 32; o <<= 1) {
        int u = __shfl_up_sync(0xffffffffu, v, o);
        if (lane >= o) v += u;
    }
    __shared__ int ws[4];
    if (lane == 31) ws[w] = v;
    __syncthreads();
    if (t == 0) {
        int a = 0;
        for (int i = 0; i < 4; i++) { int tmp = ws[i]; ws[i] = a; a += tmp; }
    }
    __syncthreads();
    v += ws[w];
    if (t < nb) g_part[t] = v - orig;    // exclusive
}

// full exclusive scan: row_ptr + fill cursors
__global__ void k_scan_full(int N, int E) {
    const int b = blockIdx.x, t = threadIdx.x;
    const int base = b * 1024 + t * 4;
    int d[4];
    int s = 0;
#pragma unroll
    for (int i = 0; i < 4; i++) {
        const int idx = base + i;
        d[i] = (idx < N) ? g_deg[idx] : 0;
        s += d[i];
    }
    const int lane = t & 31, w = t >> 5;
    int si = s;
#pragma unroll
    for (int o = 1; o < 32; o <<= 1) {
        int u = __shfl_up_sync(0xffffffffu, si, o);
        if (lane >= o) si += u;
    }
    __shared__ int ws[8];
    if (lane == 31) ws[w] = si;
    __syncthreads();
    if (t == 0) {
        int a = 0;
        for (int i = 0; i < 8; i++) { int tmp = ws[i]; ws[i] = a; a += tmp; }
    }
    __syncthreads();
    int p = si - s + ws[w] + g_part[b];  // exclusive start for this thread
#pragma unroll
    for (int i = 0; i < 4; i++) {
        const int idx = base + i;
        if (idx < N) { g_rowptr[idx] = p; g_fill[idx] = p; p += d[i]; }
    }
    if (b == 0 && t == 0) g_rowptr[N] = E;
}

__global__ void k_csrfill(const int* __restrict__ ei, int E) {
    const int t = blockIdx.x * blockDim.x + threadIdx.x;
    const int stride = gridDim.x * blockDim.x;
    for (int e = t; e < E; e += stride) {
        const int dst = ei[E + e];
        const int pos = atomicAdd(&g_fill[dst], 1);
        g_col[pos] = ei[e];
    }
}

// ---------------- pull aggregation (no atomics) -------------------------------
template <int L>
__global__ void __launch_bounds__(256)
k_agg(const float* __restrict__ xin, int N) {
    const int gw = (blockIdx.x * blockDim.x + threadIdx.x) >> 5;
    const int nw = (gridDim.x * blockDim.x) >> 5;
    const int lane = threadIdx.x & 31;
    const int c = lane * 4;
    const float* __restrict__ src = (L == 1) ? xin : (const float*)g_h;
    for (int n = gw; n < N; n += nw) {
        const int s0 = g_rowptr[n];
        const int s1 = g_rowptr[n + 1];
        float4 acc = make_float4(0.f, 0.f, 0.f, 0.f);
        int j = s0;
        for (; j + 4 <= s1; j += 4) {
            const int i0 = g_col[j], i1 = g_col[j + 1];
            const int i2 = g_col[j + 2], i3 = g_col[j + 3];
            const float4 v0 = *(const float4*)(src + (size_t)i0 * DIM + c);
            const float4 v1 = *(const float4*)(src + (size_t)i1 * DIM + c);
            const float4 v2 = *(const float4*)(src + (size_t)i2 * DIM + c);
            const float4 v3 = *(const float4*)(src + (size_t)i3 * DIM + c);
            acc.x += v0.x + v1.x + v2.x + v3.x;
            acc.y += v0.y + v1.y + v2.y + v3.y;
            acc.z += v0.z + v1.z + v2.z + v3.z;
            acc.w += v0.w + v1.w + v2.w + v3.w;
        }
        for (; j < s1; j++) {
            const int i0 = g_col[j];
            const float4 v0 = *(const float4*)(src + (size_t)i0 * DIM + c);
            acc.x += v0.x; acc.y += v0.y; acc.z += v0.z; acc.w += v0.w;
        }
        *(float4*)(g_agg + (size_t)n * DIM + c) = acc;
        if (L == 1 && lane == 0) g_cnt[n] = (float)(s1 - s0);
    }
}

// ---------------- BN finalize -------------------------------------------------
__global__ void k_bnfin(const float* __restrict__ gamma,
                        const float* __restrict__ beta, int N) {
    const int f = threadIdx.x;
    const float invN = 1.0f / (float)N;
    const float mu = g_bnsum[f] * invN;
    const float var = g_bnsq[f] * invN - mu * mu;
    const float sc = gamma[f] / sqrtf(var + 1e-5f);
    g_scale[f] = sc;
    g_shift[f] = beta[f] - mu * sc;
}

// ---------------- fused SAGE linear + epilogue -------------------------------
// C[64 x 128] per block:  C = [mean | feat] @ [Wl ; Wr] + bias, then per-row
// L2-normalize.  L==1: relu, store to g_h, accumulate BN stats.
// L==2: BN folded into both A halves; mean half's shift is gated on deg>0
// (reference: mean of a deg-0 node is exactly 0, shift must NOT be applied).
template <int L>
__global__ void __launch_bounds__(256)
k_gemm(const float* __restrict__ xin,
       const float* __restrict__ Wl, const float* __restrict__ Wr,
       const float* __restrict__ bias,
       const float* __restrict__ fcW, const float* __restrict__ fcb,
       float* __restrict__ outp, float* __restrict__ preds, int N) {
    __shared__ float As[16][72];
    __shared__ float Ws[16][128];
    __shared__ float s_invc[64];
    __shared__ float s_has[64];      // 1 if deg>0 else 0
    __shared__ float s_sc[DIM];
    __shared__ float s_sh[DIM];
    __shared__ float s_sum[DIM];
    __shared__ float s_sq[DIM];

    const int tid = threadIdx.x;
    const int r0 = blockIdx.x * 64;
    const int w = tid >> 5;
    const int lane = tid & 31;

    if (tid < 64) {
        const int n = min(r0 + tid, N - 1);
        const float c = g_cnt[n];
        s_invc[tid] = 1.0f / fmaxf(c, 1.0f);
        s_has[tid] = (c > 0.f) ? 1.0f : 0.0f;
    }
    if (L == 2) {
        if (tid < DIM) { s_sc[tid] = g_scale[tid]; s_sh[tid] = g_shift[tid]; }
    } else {
        if (tid < DIM) { s_sum[tid] = 0.f; s_sq[tid] = 0.f; }
    }
    __syncthreads();

    float acc[8][4];
#pragma unroll
    for (int i = 0; i < 8; i++) {
        acc[i][0] = 0.f; acc[i][1] = 0.f; acc[i][2] = 0.f; acc[i][3] = 0.f;
    }

    const int lrow = tid >> 2;
    const int kq = (tid & 3) * 4;
    const int nrow = min(r0 + lrow, N - 1);
    const float* __restrict__ aggrow = g_agg + (size_t)nrow * DIM;
    const float* __restrict__ xrow =
        (L == 1 ? xin : (const float*)g_h) + (size_t)nrow * DIM;
    const float invc = s_invc[lrow];
    const float hasf = s_has[lrow];

    const int wc = lane * 4;
    const int w8 = w * 8;

    for (int kc = 0; kc < 2 * DIM; kc += 16) {
        {
            const int k = kc + kq;
            float4 v;
            if (k < DIM) {
                v = *(const float4*)(aggrow + k);
                v.x *= invc; v.y *= invc; v.z *= invc; v.w *= invc;
                if (L == 2) {  // mean(bn(h)) = sc*mean(h) + [deg>0]*sh
                    v.x = v.x * s_sc[k + 0] + hasf * s_sh[k + 0];
                    v.y = v.y * s_sc[k + 1] + hasf * s_sh[k + 1];
                    v.z = v.z * s_sc[k + 2] + hasf * s_sh[k + 2];
                    v.w = v.w * s_sc[k + 3] + hasf * s_sh[k + 3];
                }
            } else {
                const int k2 = k - DIM;
                v = *(const float4*)(xrow + k2);
                if (L == 2) {
                    v.x = v.x * s_sc[k2 + 0] + s_sh[k2 + 0];
                    v.y = v.y * s_sc[k2 + 1] + s_sh[k2 + 1];
                    v.z = v.z * s_sc[k2 + 2] + s_sh[k2 + 2];
                    v.w = v.w * s_sc[k2 + 3] + s_sh[k2 + 3];
                }
            }
            As[kq + 0][lrow] = v.x;
            As[kq + 1][lrow] = v.y;
            As[kq + 2][lrow] = v.z;
            As[kq + 3][lrow] = v.w;
        }
#pragma unroll
        for (int h2 = 0; h2 < 2; h2++) {
            const int kk = w + h2 * 8;
            const int k = kc + kk;
            const float* Wp = (k < DIM) ? (Wl + (size_t)k * DIM + wc)
                                        : (Wr + (size_t)(k - DIM) * DIM + wc);
            *(float4*)&Ws[kk][wc] = *(const float4*)Wp;
        }
        __syncthreads();
#pragma unroll
        for (int kk = 0; kk < 16; kk++) {
            const float4 a0 = *(const float4*)&As[kk][w8];
            const float4 a1 = *(const float4*)&As[kk][w8 + 4];
            const float4 b4 = *(const float4*)&Ws[kk][wc];
            const float a[8] = {a0.x, a0.y, a0.z, a0.w, a1.x, a1.y, a1.z, a1.w};
#pragma unroll
            for (int i = 0; i < 8; i++) {
                acc[i][0] += a[i] * b4.x;
                acc[i][1] += a[i] * b4.y;
                acc[i][2] += a[i] * b4.z;
                acc[i][3] += a[i] * b4.w;
            }
        }
        __syncthreads();
    }

    const float4 bb = *(const float4*)(bias + wc);
    float fw0 = 0.f, fw1 = 0.f, fw2 = 0.f, fw3 = 0.f;
    if (L == 2) {
        if (wc + 0 < 64) fw0 = fcW[wc + 0];
        if (wc + 1 < 64) fw1 = fcW[wc + 1];
        if (wc + 2 < 64) fw2 = fcW[wc + 2];
        if (wc + 3 < 64) fw3 = fcW[wc + 3];
    }
    float* __restrict__ op =
        (L == 1) ? (float*)g_h : (outp ? outp : (float*)g_h);
    float* __restrict__ pp = preds ? preds : (float*)g_preds_fb;

    float ps[4] = {0.f, 0.f, 0.f, 0.f}, qs[4] = {0.f, 0.f, 0.f, 0.f};
#pragma unroll
    for (int i = 0; i < 8; i++) {
        const int r = r0 + w8 + i;
        float v0 = acc[i][0] + bb.x;
        float v1 = acc[i][1] + bb.y;
        float v2 = acc[i][2] + bb.z;
        float v3 = acc[i][3] + bb.w;
        float ss = v0 * v0 + v1 * v1 + v2 * v2 + v3 * v3;
#pragma unroll
        for (int o = 16; o > 0; o >>= 1) ss += __shfl_xor_sync(0xffffffffu, ss, o);
        const float inv = 1.0f / fmaxf(sqrtf(ss), 1e-12f);
        v0 *= inv; v1 *= inv; v2 *= inv; v3 *= inv;
        if (L == 1) {
            v0 = fmaxf(v0, 0.f); v1 = fmaxf(v1, 0.f);
            v2 = fmaxf(v2, 0.f); v3 = fmaxf(v3, 0.f);
            if (r < N) {
                *(float4*)(op + (size_t)r * DIM + wc) = make_float4(v0, v1, v2, v3);
                ps[0] += v0; ps[1] += v1; ps[2] += v2; ps[3] += v3;
                qs[0] += v0 * v0; qs[1] += v1 * v1;
                qs[2] += v2 * v2; qs[3] += v3 * v3;
            }
        } else {
            if (r < N) {
                *(float4*)(op + (size_t)r * DIM + wc) = make_float4(v0, v1, v2, v3);
                float pd = v0 * fw0 + v1 * fw1 + v2 * fw2 + v3 * fw3;
#pragma unroll
                for (int o = 16; o > 0; o >>= 1)
                    pd += __shfl_xor_sync(0xffffffffu, pd, o);
                if (lane == 0) pp[r] = pd + fcb[0];
            }
        }
    }
    if (L == 1) {
        atomicAdd(&s_sum[wc + 0], ps[0]); atomicAdd(&s_sum[wc + 1], ps[1]);
        atomicAdd(&s_sum[wc + 2], ps[2]); atomicAdd(&s_sum[wc + 3], ps[3]);
        atomicAdd(&s_sq[wc + 0], qs[0]);  atomicAdd(&s_sq[wc + 1], qs[1]);
        atomicAdd(&s_sq[wc + 2], qs[2]);  atomicAdd(&s_sq[wc + 3], qs[3]);
        __syncthreads();
        if (tid < DIM) {
            atomicAdd(&g_bnsum[tid], s_sum[tid]);
            atomicAdd(&g_bnsq[tid], s_sq[tid]);
        }
    }
}

// ---------------- launch ------------------------------------------------------
extern "C" void kernel_launch(void* const* d_in, const int* in_sizes, int n_in,
                              void* d_out, int out_size) {
    const float* x     = (const float*)d_in[0];
    const int*   ei    = (const int*)d_in[1];
    const float* W1l   = (const float*)d_in[2];
    const float* b1l   = (const float*)d_in[3];
    const float* W1r   = (const float*)d_in[4];
    const float* gamma = (const float*)d_in[5];
    const float* beta  = (const float*)d_in[6];
    const float* W2l   = (const float*)d_in[7];
    const float* b2l   = (const float*)d_in[8];
    const float* W2r   = (const float*)d_in[9];
    const float* fcW   = (const float*)d_in[10];
    const float* fcb   = (const float*)d_in[11];

    const int N = in_sizes[0] / DIM;
    const int E = in_sizes[1] / 2;

    float* predsP = nullptr;
    float* embedP = nullptr;
    const long long need = (long long)N * DIM + N;
    if ((long long)out_size >= need) {
        predsP = (float*)d_out;
        embedP = (float*)d_out + N;
    } else if ((long long)out_size >= (long long)N * DIM) {
        embedP = (float*)d_out;
    } else {
        predsP = (float*)d_out;
    }

    const int nb = (N + 1023) / 1024;          // scan blocks (<= NBMAX)
    const int ge = (E + 256 * 8 - 1) / (256 * 8);
    const int gg = (N + 63) / 64;

    // CSR build (reused for both layers)
    k_init<<<(N + 255) / 256, 256>>>(N);
    k_count<<<ge * 8, 256>>>(ei, E);
    k_scan_part<<<nb, 256>>>(N);
    k_scan_top<<<1, 128>>>(nb);
    k_scan_full<<<nb, 256>>>(N, E);
    k_csrfill<<<ge * 8, 256>>>(ei, E);

    // layer 1
    k_agg<1><<<4096, 256>>>(x, N);
    k_gemm<1><<<gg, 256>>>(x, W1l, W1r, b1l, nullptr, nullptr, nullptr, nullptr, N);
    k_bnfin<<<1, 128>>>(gamma, beta, N);

    // layer 2
    k_agg<2><<<4096, 256>>>(nullptr, N);
    k_gemm<2><<<gg, 256>>>(nullptr, W2l, W2r, b2l, fcW, fcb, embedP, predsP, N);
}

// round 5
// speedup vs baseline: 2.4426x; 1.6147x over previous
#include <cuda_runtime.h>
#include <cuda_bf16.h>
#include <cstdint>

#define DIM 128
#define NMAX 100000
#define EMAX 600000
#define NBMAX 128

// ---------------- static device scratch --------------------------------------
__device__ float g_agg[(size_t)NMAX * DIM];
__device__ float g_cnt[NMAX];
__device__ float g_h[(size_t)NMAX * DIM];
__device__ float g_bnsum[DIM];
__device__ float g_bnsq[DIM];
__device__ float g_scale[DIM];
__device__ float g_shift[DIM];
__device__ float g_preds_fb[NMAX];
__device__ int   g_deg[NMAX];
__device__ int   g_rowptr[NMAX + 1];
__device__ int   g_fill[NMAX];
__device__ int   g_col[EMAX];
__device__ int   g_part[NBMAX];
// pre-split transposed weights: [layer][n(128)][k(256)] bf16 hi/lo
__device__ __nv_bfloat16 g_wthi[2 * 128 * 256];
__device__ __nv_bfloat16 g_wtlo[2 * 128 * 256];

// ---------------- CSR build ---------------------------------------------------
__global__ void k_init(int N) {
    const int t = blockIdx.x * blockDim.x + threadIdx.x;
    const int stride = gridDim.x * blockDim.x;
    for (int i = t; i < N; i += stride) g_deg[i] = 0;
    if (t < DIM) { g_bnsum[t] = 0.f; g_bnsq[t] = 0.f; }
}

__global__ void k_count(const int* __restrict__ ei, int E) {
    const int t = blockIdx.x * blockDim.x + threadIdx.x;
    const int stride = gridDim.x * blockDim.x;
    for (int e = t; e < E; e += stride) atomicAdd(&g_deg[ei[E + e]], 1);
}

__global__ void k_scan_part(int N) {
    const int b = blockIdx.x, t = threadIdx.x;
    const int base = b * 1024 + t * 4;
    int s = 0;
#pragma unroll
    for (int i = 0; i < 4; i++) {
        const int idx = base + i;
        if (idx < N) s += g_deg[idx];
    }
#pragma unroll
    for (int o = 16; o > 0; o >>= 1) s += __shfl_xor_sync(0xffffffffu, s, o);
    __shared__ int ws[8];
    if ((t & 31) == 0) ws[t >> 5] = s;
    __syncthreads();
    if (t == 0) {
        int a = 0;
        for (int i = 0; i < 8; i++) a += ws[i];
        g_part[b] = a;
    }
}

__global__ void k_scan_top(int nb) {
    const int t = threadIdx.x;
    const int lane = t & 31, w = t >> 5;
    int orig = (t < nb) ? g_part[t] : 0;
    int v = orig;
#pragma unroll
    for (int o = 1; o < 32; o <<= 1) {
        int u = __shfl_up_sync(0xffffffffu, v, o);
        if (lane >= o) v += u;
    }
    __shared__ int ws[4];
    if (lane == 31) ws[w] = v;
    __syncthreads();
    if (t == 0) {
        int a = 0;
        for (int i = 0; i < 4; i++) { int tmp = ws[i]; ws[i] = a; a += tmp; }
    }
    __syncthreads();
    v += ws[w];
    if (t < nb) g_part[t] = v - orig;
}

__global__ void k_scan_full(int N, int E) {
    const int b = blockIdx.x, t = threadIdx.x;
    const int base = b * 1024 + t * 4;
    int d[4];
    int s = 0;
#pragma unroll
    for (int i = 0; i < 4; i++) {
        const int idx = base + i;
        d[i] = (idx < N) ? g_deg[idx] : 0;
        s += d[i];
    }
    const int lane = t & 31, w = t >> 5;
    int si = s;
#pragma unroll
    for (int o = 1; o < 32; o <<= 1) {
        int u = __shfl_up_sync(0xffffffffu, si, o);
        if (lane >= o) si += u;
    }
    __shared__ int ws[8];
    if (lane == 31) ws[w] = si;
    __syncthreads();
    if (t == 0) {
        int a = 0;
        for (int i = 0; i < 8; i++) { int tmp = ws[i]; ws[i] = a; a += tmp; }
    }
    __syncthreads();
    int p = si - s + ws[w] + g_part[b];
#pragma unroll
    for (int i = 0; i < 4; i++) {
        const int idx = base + i;
        if (idx < N) { g_rowptr[idx] = p; g_fill[idx] = p; p += d[i]; }
    }
    if (b == 0 && t == 0) g_rowptr[N] = E;
}

__global__ void k_csrfill(const int* __restrict__ ei, int E) {
    const int t = blockIdx.x * blockDim.x + threadIdx.x;
    const int stride = gridDim.x * blockDim.x;
    for (int e = t; e < E; e += stride) {
        const int dst = ei[E + e];
        const int pos = atomicAdd(&g_fill[dst], 1);
        g_col[pos] = ei[e];
    }
}

// ---------------- weight pre-split (transposed [n][k], bf16 hi/lo) -----------
__global__ void k_wprep(const float* __restrict__ W1l, const float* __restrict__ W1r,
                        const float* __restrict__ W2l, const float* __restrict__ W2r) {
    const int t = blockIdx.x * blockDim.x + threadIdx.x;
    if (t >= 2 * 128 * 256) return;
    const int layer = t >> 15;
    const int rem = t & 32767;
    const int n = rem >> 8;     // 0..127
    const int k = rem & 255;    // 0..255
    const float* Wl = layer ? W2l : W1l;
    const float* Wr = layer ? W2r : W1r;
    const float val = (k < 128) ? Wl[k * 128 + n] : Wr[(k - 128) * 128 + n];
    const __nv_bfloat16 hi = __float2bfloat16_rn(val);
    const __nv_bfloat16 lo = __float2bfloat16_rn(val - __bfloat162float(hi));
    g_wthi[t] = hi;
    g_wtlo[t] = lo;
}

// ---------------- pull aggregation (no atomics) -------------------------------
template <int L>
__global__ void __launch_bounds__(256)
k_agg(const float* __restrict__ xin, int N) {
    const int gw = (blockIdx.x * blockDim.x + threadIdx.x) >> 5;
    const int nw = (gridDim.x * blockDim.x) >> 5;
    const int lane = threadIdx.x & 31;
    const int c = lane * 4;
    const float* __restrict__ src = (L == 1) ? xin : (const float*)g_h;
    for (int n = gw; n < N; n += nw) {
        const int s0 = g_rowptr[n];
        const int s1 = g_rowptr[n + 1];
        float4 acc = make_float4(0.f, 0.f, 0.f, 0.f);
        int j = s0;
        for (; j + 4 <= s1; j += 4) {
            const int i0 = g_col[j], i1 = g_col[j + 1];
            const int i2 = g_col[j + 2], i3 = g_col[j + 3];
            const float4 v0 = *(const float4*)(src + (size_t)i0 * DIM + c);
            const float4 v1 = *(const float4*)(src + (size_t)i1 * DIM + c);
            const float4 v2 = *(const float4*)(src + (size_t)i2 * DIM + c);
            const float4 v3 = *(const float4*)(src + (size_t)i3 * DIM + c);
            acc.x += v0.x + v1.x + v2.x + v3.x;
            acc.y += v0.y + v1.y + v2.y + v3.y;
            acc.z += v0.z + v1.z + v2.z + v3.z;
            acc.w += v0.w + v1.w + v2.w + v3.w;
        }
        for (; j < s1; j++) {
            const int i0 = g_col[j];
            const float4 v0 = *(const float4*)(src + (size_t)i0 * DIM + c);
            acc.x += v0.x; acc.y += v0.y; acc.z += v0.z; acc.w += v0.w;
        }
        *(float4*)(g_agg + (size_t)n * DIM + c) = acc;
        if (L == 1 && lane == 0) g_cnt[n] = (float)(s1 - s0);
    }
}

// ---------------- BN finalize -------------------------------------------------
__global__ void k_bnfin(const float* __restrict__ gamma,
                        const float* __restrict__ beta, int N) {
    const int f = threadIdx.x;
    const float invN = 1.0f / (float)N;
    const float mu = g_bnsum[f] * invN;
    const float var = g_bnsq[f] * invN - mu * mu;
    const float sc = gamma[f] / sqrtf(var + 1e-5f);
    g_scale[f] = sc;
    g_shift[f] = beta[f] - mu * sc;
}

// ---------------- tensor-core fused SAGE linear ------------------------------
// bf16 split-precision (hi+lo, 3 products) m16n8k16 MMA.
// Block tile 64x128, 8 warps: warp = (wm = w&1)*32 rows x (wn = w>>1)*32 cols,
// each warp 2 m16-tiles x 4 n8-tiles. K = 256 in 8 chunks of 32.
#define MMA_BF16(d, a, b0, b1)                                              \
    asm volatile(                                                           \
        "mma.sync.aligned.m16n8k16.row.col.f32.bf16.bf16.f32 "              \
        "{%0,%1,%2,%3}, {%4,%5,%6,%7}, {%8,%9}, {%0,%1,%2,%3};"             \
        : "+f"(d[0]), "+f"(d[1]), "+f"(d[2]), "+f"(d[3])                    \
        : "r"(a[0]), "r"(a[1]), "r"(a[2]), "r"(a[3]), "r"(b0), "r"(b1))

template <int L>
__global__ void __launch_bounds__(256)
k_gemm(const float* __restrict__ xin, const float* __restrict__ bias,
       const float* __restrict__ fcW, const float* __restrict__ fcb,
       float* __restrict__ outp, float* __restrict__ preds, int N) {
    // shared union: stage1 tiles (30720B) / stage2 C tile (64*132*4 = 33792B)
    __shared__ __align__(16) char smraw[33792];
    __nv_bfloat16* As_hi = (__nv_bfloat16*)smraw;              // 64 x 40
    __nv_bfloat16* As_lo = (__nv_bfloat16*)(smraw + 5120);
    __nv_bfloat16* Ws_hi = (__nv_bfloat16*)(smraw + 10240);    // 128 x 40
    __nv_bfloat16* Ws_lo = (__nv_bfloat16*)(smraw + 20480);
    float* Cs = (float*)smraw;                                 // 64 x 132
    __shared__ float s_invc[64];
    __shared__ float s_has[64];
    __shared__ float s_sc[DIM];
    __shared__ float s_sh[DIM];
    __shared__ float s_sum[DIM];
    __shared__ float s_sq[DIM];

    const int tid = threadIdx.x;
    const int r0 = blockIdx.x * 64;
    const int w = tid >> 5;
    const int lane = tid & 31;

    if (tid < 64) {
        const int n = min(r0 + tid, N - 1);
        const float c = g_cnt[n];
        s_invc[tid] = 1.0f / fmaxf(c, 1.0f);
        s_has[tid] = (c > 0.f) ? 1.0f : 0.0f;
    }
    if (L == 2) {
        if (tid < DIM) { s_sc[tid] = g_scale[tid]; s_sh[tid] = g_shift[tid]; }
    } else {
        if (tid < DIM) { s_sum[tid] = 0.f; s_sq[tid] = 0.f; }
    }
    __syncthreads();

    // A fill mapping
    const int arow = tid >> 2;             // 0..63
    const int kq8 = (tid & 3) * 8;         // 0,8,16,24
    const int nrow = min(r0 + arow, N - 1);
    const float* __restrict__ aggrow = g_agg + (size_t)nrow * DIM;
    const float* __restrict__ xrow =
        (L == 1 ? xin : (const float*)g_h) + (size_t)nrow * DIM;
    const float invc = s_invc[arow];
    const float hasf = s_has[arow];

    const __nv_bfloat16* __restrict__ wt_hi = g_wthi + (size_t)(L - 1) * 32768;
    const __nv_bfloat16* __restrict__ wt_lo = g_wtlo + (size_t)(L - 1) * 32768;

    const int wm = w & 1;                  // row half
    const int wn = w >> 1;                 // col quarter

    float acc[2][4][4];
#pragma unroll
    for (int mt = 0; mt < 2; mt++)
#pragma unroll
        for (int nt = 0; nt < 4; nt++)
#pragma unroll
            for (int i = 0; i < 4; i++) acc[mt][nt][i] = 0.f;

    for (int kc = 0; kc < 2 * DIM; kc += 32) {
        // ---- A tile fill: fp32 compute -> bf16 hi/lo split ----
        {
            const int k = kc + kq8;
            float v[8];
            if (k < DIM) {
                const float4 p = *(const float4*)(aggrow + k);
                const float4 q = *(const float4*)(aggrow + k + 4);
                v[0] = p.x * invc; v[1] = p.y * invc; v[2] = p.z * invc; v[3] = p.w * invc;
                v[4] = q.x * invc; v[5] = q.y * invc; v[6] = q.z * invc; v[7] = q.w * invc;
                if (L == 2) {
#pragma unroll
                    for (int j = 0; j < 8; j++)
                        v[j] = v[j] * s_sc[k + j] + hasf * s_sh[k + j];
                }
            } else {
                const int k2 = k - DIM;
                const float4 p = *(const float4*)(xrow + k2);
                const float4 q = *(const float4*)(xrow + k2 + 4);
                v[0] = p.x; v[1] = p.y; v[2] = p.z; v[3] = p.w;
                v[4] = q.x; v[5] = q.y; v[6] = q.z; v[7] = q.w;
                if (L == 2) {
#pragma unroll
                    for (int j = 0; j < 8; j++)
                        v[j] = v[j] * s_sc[k2 + j] + s_sh[k2 + j];
                }
            }
            uint32_t* dh = (uint32_t*)(As_hi + arow * 40 + kq8);
            uint32_t* dl = (uint32_t*)(As_lo + arow * 40 + kq8);
#pragma unroll
            for (int j = 0; j < 4; j++) {
                const __nv_bfloat16 h0 = __float2bfloat16_rn(v[2 * j]);
                const __nv_bfloat16 h1 = __float2bfloat16_rn(v[2 * j + 1]);
                const __nv_bfloat16 l0 =
                    __float2bfloat16_rn(v[2 * j] - __bfloat162float(h0));
                const __nv_bfloat16 l1 =
                    __float2bfloat16_rn(v[2 * j + 1] - __bfloat162float(h1));
                dh[j] = (uint32_t)__bfloat16_as_ushort(h0) |
                        ((uint32_t)__bfloat16_as_ushort(h1) << 16);
                dl[j] = (uint32_t)__bfloat16_as_ushort(l0) |
                        ((uint32_t)__bfloat16_as_ushort(l1) << 16);
            }
        }
        // ---- W tile fill from pre-split global (straight copy) ----
#pragma unroll
        for (int r = 0; r < 2; r++) {
            const int idx = tid + r * 256;           // 0..511
            const int n = idx >> 2, qq = idx & 3;    // 16B quad
            *(float4*)((char*)Ws_hi + n * 80 + qq * 16) =
                *(const float4*)(wt_hi + n * 256 + kc + qq * 8);
            *(float4*)((char*)Ws_lo + n * 80 + qq * 16) =
                *(const float4*)(wt_lo + n * 256 + kc + qq * 8);
        }
        __syncthreads();

        // ---- compute: 2 k16 steps ----
#pragma unroll
        for (int ks = 0; ks < 2; ks++) {
            uint32_t ah[2][4], al[2][4];
#pragma unroll
            for (int mt = 0; mt < 2; mt++) {
                const int rb = wm * 32 + mt * 16 + (lane >> 2);
                const uint32_t* p0h = (const uint32_t*)(As_hi + rb * 40) + ks * 8 + (lane & 3);
                const uint32_t* p1h = (const uint32_t*)(As_hi + (rb + 8) * 40) + ks * 8 + (lane & 3);
                ah[mt][0] = p0h[0]; ah[mt][1] = p1h[0];
                ah[mt][2] = p0h[4]; ah[mt][3] = p1h[4];
                const uint32_t* p0l = (const uint32_t*)(As_lo + rb * 40) + ks * 8 + (lane & 3);
                const uint32_t* p1l = (const uint32_t*)(As_lo + (rb + 8) * 40) + ks * 8 + (lane & 3);
                al[mt][0] = p0l[0]; al[mt][1] = p1l[0];
                al[mt][2] = p0l[4]; al[mt][3] = p1l[4];
            }
#pragma unroll
            for (int nt = 0; nt < 4; nt++) {
                const int n = wn * 32 + nt * 8 + (lane >> 2);
                const uint32_t* bph = (const uint32_t*)(Ws_hi + n * 40) + ks * 8 + (lane & 3);
                const uint32_t* bpl = (const uint32_t*)(Ws_lo + n * 40) + ks * 8 + (lane & 3);
                const uint32_t bh0 = bph[0], bh1 = bph[4];
                const uint32_t bl0 = bpl[0], bl1 = bpl[4];
#pragma unroll
                for (int mt = 0; mt < 2; mt++) {
                    MMA_BF16(acc[mt][nt], ah[mt], bh0, bh1);
                    MMA_BF16(acc[mt][nt], ah[mt], bl0, bl1);
                    MMA_BF16(acc[mt][nt], al[mt], bh0, bh1);
                }
            }
        }
        __syncthreads();
    }

    // ---- store accumulators to shared C tile (aliases A/W tiles) ----
#pragma unroll
    for (int mt = 0; mt < 2; mt++)
#pragma unroll
        for (int nt = 0; nt < 4; nt++) {
            const int row = wm * 32 + mt * 16 + (lane >> 2);
            const int col = wn * 32 + nt * 8 + (lane & 3) * 2;
            Cs[row * 132 + col]           = acc[mt][nt][0];
            Cs[row * 132 + col + 1]       = acc[mt][nt][1];
            Cs[(row + 8) * 132 + col]     = acc[mt][nt][2];
            Cs[(row + 8) * 132 + col + 1] = acc[mt][nt][3];
        }
    __syncthreads();

    // ---- epilogue (identical math to R3, reading Cs) ----
    const int wc = lane * 4;
    const int w8 = w * 8;
    const float4 bb = *(const float4*)(bias + wc);
    float fw0 = 0.f, fw1 = 0.f, fw2 = 0.f, fw3 = 0.f;
    if (L == 2) {
        if (wc + 0 < 64) fw0 = fcW[wc + 0];
        if (wc + 1 < 64) fw1 = fcW[wc + 1];
        if (wc + 2 < 64) fw2 = fcW[wc + 2];
        if (wc + 3 < 64) fw3 = fcW[wc + 3];
    }
    float* __restrict__ op =
        (L == 1) ? (float*)g_h : (outp ? outp : (float*)g_h);
    float* __restrict__ pp = preds ? preds : (float*)g_preds_fb;

    float ps[4] = {0.f, 0.f, 0.f, 0.f}, qs[4] = {0.f, 0.f, 0.f, 0.f};
#pragma unroll
    for (int i = 0; i < 8; i++) {
        const int row = w8 + i;
        const int r = r0 + row;
        const float4 cv = *(const float4*)&Cs[row * 132 + wc];
        float v0 = cv.x + bb.x;
        float v1 = cv.y + bb.y;
        float v2 = cv.z + bb.z;
        float v3 = cv.w + bb.w;
        float ss = v0 * v0 + v1 * v1 + v2 * v2 + v3 * v3;
#pragma unroll
        for (int o = 16; o > 0; o >>= 1) ss += __shfl_xor_sync(0xffffffffu, ss, o);
        const float inv = 1.0f / fmaxf(sqrtf(ss), 1e-12f);
        v0 *= inv; v1 *= inv; v2 *= inv; v3 *= inv;
        if (L == 1) {
            v0 = fmaxf(v0, 0.f); v1 = fmaxf(v1, 0.f);
            v2 = fmaxf(v2, 0.f); v3 = fmaxf(v3, 0.f);
            if (r < N) {
                *(float4*)(op + (size_t)r * DIM + wc) = make_float4(v0, v1, v2, v3);
                ps[0] += v0; ps[1] += v1; ps[2] += v2; ps[3] += v3;
                qs[0] += v0 * v0; qs[1] += v1 * v1;
                qs[2] += v2 * v2; qs[3] += v3 * v3;
            }
        } else {
            if (r < N) {
                *(float4*)(op + (size_t)r * DIM + wc) = make_float4(v0, v1, v2, v3);
                float pd = v0 * fw0 + v1 * fw1 + v2 * fw2 + v3 * fw3;
#pragma unroll
                for (int o = 16; o > 0; o >>= 1)
                    pd += __shfl_xor_sync(0xffffffffu, pd, o);
                if (lane == 0) pp[r] = pd + fcb[0];
            }
        }
    }
    if (L == 1) {
        atomicAdd(&s_sum[wc + 0], ps[0]); atomicAdd(&s_sum[wc + 1], ps[1]);
        atomicAdd(&s_sum[wc + 2], ps[2]); atomicAdd(&s_sum[wc + 3], ps[3]);
        atomicAdd(&s_sq[wc + 0], qs[0]);  atomicAdd(&s_sq[wc + 1], qs[1]);
        atomicAdd(&s_sq[wc + 2], qs[2]);  atomicAdd(&s_sq[wc + 3], qs[3]);
        __syncthreads();
        if (tid < DIM) {
            atomicAdd(&g_bnsum[tid], s_sum[tid]);
            atomicAdd(&g_bnsq[tid], s_sq[tid]);
        }
    }
}

// ---------------- launch ------------------------------------------------------
extern "C" void kernel_launch(void* const* d_in, const int* in_sizes, int n_in,
                              void* d_out, int out_size) {
    const float* x     = (const float*)d_in[0];
    const int*   ei    = (const int*)d_in[1];
    const float* W1l   = (const float*)d_in[2];
    const float* b1l   = (const float*)d_in[3];
    const float* W1r   = (const float*)d_in[4];
    const float* gamma = (const float*)d_in[5];
    const float* beta  = (const float*)d_in[6];
    const float* W2l   = (const float*)d_in[7];
    const float* b2l   = (const float*)d_in[8];
    const float* W2r   = (const float*)d_in[9];
    const float* fcW   = (const float*)d_in[10];
    const float* fcb   = (const float*)d_in[11];

    const int N = in_sizes[0] / DIM;
    const int E = in_sizes[1] / 2;

    float* predsP = nullptr;
    float* embedP = nullptr;
    const long long need = (long long)N * DIM + N;
    if ((long long)out_size >= need) {
        predsP = (float*)d_out;
        embedP = (float*)d_out + N;
    } else if ((long long)out_size >= (long long)N * DIM) {
        embedP = (float*)d_out;
    } else {
        predsP = (float*)d_out;
    }

    const int nb = (N + 1023) / 1024;
    const int ge = (E + 256 * 8 - 1) / (256 * 8);
    const int gg = (N + 63) / 64;

    // weight pre-split + CSR build
    k_wprep<<<(2 * 128 * 256 + 255) / 256, 256>>>(W1l, W1r, W2l, W2r);
    k_init<<<(N + 255) / 256, 256>>>(N);
    k_count<<<ge * 8, 256>>>(ei, E);
    k_scan_part<<<nb, 256>>>(N);
    k_scan_top<<<1, 128>>>(nb);
    k_scan_full<<<nb, 256>>>(N, E);
    k_csrfill<<<ge * 8, 256>>>(ei, E);

    // layer 1
    k_agg<1><<<4096, 256>>>(x, N);
    k_gemm<1><<<gg, 256>>>(x, b1l, nullptr, nullptr, nullptr, nullptr, N);
    k_bnfin<<<1, 128>>>(gamma, beta, N);

    // layer 2
    k_agg<2><<<4096, 256>>>(nullptr, N);
    k_gemm<2><<<gg, 256>>>(nullptr, b2l, fcW, fcb, embedP, predsP, N);
}